// round 14
// baseline (speedup 1.0000x reference)
#include <cuda_runtime.h>
#include <cuda_bf16.h>
#include <math.h>
#include <stdint.h>

#define Bz   32
#define Tt   32
#define Ss   256
#define Vv   32000
#define Ee   256
#define Hh   512
#define OOV  50
#define VEXT 32050
#define NEGC 1.0e12f
#define NCTA 148
#define NTHR 256

// ---------------- device state ----------------
__device__ float g_mem[Bz * Ss * Hh];        // memories [B,S,H] (16 MB)
__device__ float g_h[Bz * Hh];
__device__ float g_c[Bz * Hh];
__device__ float g_ctx[Bz * Hh];
__device__ float g_copy[Bz * VEXT];
__device__ float g_Wbig[1280 * 2048];        // [red_W@Wx ; Wh]
__device__ float g_bcomb[2048];
__device__ float g_gpart[4 * Bz * 2048];
__device__ float g_cpart[4 * Bz * 512];
__device__ float g_energy[Bz * Ss];
__device__ float g_attnw[Bz * Ss];
// packed logit weight: entry (v, kt, qc) = {hi[kt*8+qc], hi[kt*8+qc+4], lo[kt*8+qc], lo[kt*8+qc+4]}
// (u32 words of bf16x2 pairs; 65.5 MB total)
__device__ __align__(16) uint4 g_Wpk[(size_t)Vv * 32 * 4];
__device__ __align__(16) __nv_bfloat16 g_shi[Bz * Hh];
__device__ __align__(16) __nv_bfloat16 g_slo[Bz * Hh];
__device__ unsigned int g_bar_cnt;
__device__ unsigned int g_bar_gen;

// ---------------- global barrier (sense-reversing) ----------------
__device__ __forceinline__ void gbar() {
    __syncthreads();
    if (threadIdx.x == 0) {
        volatile unsigned int* vgen = &g_bar_gen;
        unsigned int gen = *vgen;
        __threadfence();
        unsigned int arrived = atomicAdd(&g_bar_cnt, 1u);
        if (arrived == NCTA - 1) {
            g_bar_cnt = 0;
            __threadfence();
            *vgen = gen + 1;
        } else {
            while (*vgen == gen) { }
            __threadfence();
        }
    }
    __syncthreads();
}

__device__ __forceinline__ void bf16split(float v, __nv_bfloat16* hi, __nv_bfloat16* lo) {
    __nv_bfloat16 h = __float2bfloat16(v);
    *hi = h;
    *lo = __float2bfloat16(v - __bfloat162float(h));
}

// ---------------- launch 0: init ----------------
__global__ void k_init(const float* __restrict__ h0, const float* __restrict__ c0) {
    int idx = blockIdx.x * 256 + threadIdx.x;     // 16384
    g_h[idx] = h0[idx];
    g_c[idx] = c0[idx];
    g_ctx[idx] = 0.f;
    if (idx == 0) { g_bar_cnt = 0; g_bar_gen = 0; }
}

// ---------------- launch 1: reset copy buffer ----------------
__global__ void k_resetfull() {
    int idx = blockIdx.x * 256 + threadIdx.x;
    if (idx < Bz * VEXT) g_copy[idx] = -NEGC;
}

// ---------------- launches 2,3: tiled GEMM (setup) ----------------
__global__ void __launch_bounds__(256) k_gemm(const float* __restrict__ A,
                                              const float* __restrict__ B,
                                              const float* __restrict__ bias,
                                              int M, int K, int N, int dst) {
    float* C = dst ? g_Wbig : g_mem;
    __shared__ float As[16][65];
    __shared__ float Bs[16][64];
    int tx = threadIdx.x & 15, ty = threadIdx.x >> 4;
    int row0 = blockIdx.y * 64, col0 = blockIdx.x * 64;
    int lrow = threadIdx.x >> 2;
    int kq   = (threadIdx.x & 3) * 4;
    int bkk  = threadIdx.x >> 4;
    int bcq  = (threadIdx.x & 15) * 4;
    float acc[4][4] = {};
    for (int k0 = 0; k0 < K; k0 += 16) {
        float4 av = *(const float4*)&A[(size_t)(row0 + lrow) * K + k0 + kq];
        float4 bv = *(const float4*)&B[(size_t)(k0 + bkk) * N + col0 + bcq];
        As[kq + 0][lrow] = av.x; As[kq + 1][lrow] = av.y;
        As[kq + 2][lrow] = av.z; As[kq + 3][lrow] = av.w;
        *(float4*)&Bs[bkk][bcq] = bv;
        __syncthreads();
#pragma unroll
        for (int kk = 0; kk < 16; kk++) {
            float a0 = As[kk][ty * 4 + 0], a1 = As[kk][ty * 4 + 1];
            float a2 = As[kk][ty * 4 + 2], a3 = As[kk][ty * 4 + 3];
            float4 b4 = *(const float4*)&Bs[kk][tx * 4];
            acc[0][0] += a0 * b4.x; acc[0][1] += a0 * b4.y; acc[0][2] += a0 * b4.z; acc[0][3] += a0 * b4.w;
            acc[1][0] += a1 * b4.x; acc[1][1] += a1 * b4.y; acc[1][2] += a1 * b4.z; acc[1][3] += a1 * b4.w;
            acc[2][0] += a2 * b4.x; acc[2][1] += a2 * b4.y; acc[2][2] += a2 * b4.z; acc[2][3] += a2 * b4.w;
            acc[3][0] += a3 * b4.x; acc[3][1] += a3 * b4.y; acc[3][2] += a3 * b4.z; acc[3][3] += a3 * b4.w;
        }
        __syncthreads();
    }
    int c = col0 + tx * 4;
    float4 bb = bias ? *(const float4*)&bias[c] : make_float4(0.f, 0.f, 0.f, 0.f);
#pragma unroll
    for (int i = 0; i < 4; i++) {
        int row = row0 + ty * 4 + i;
        float4 o;
        o.x = acc[i][0] + bb.x; o.y = acc[i][1] + bb.y;
        o.z = acc[i][2] + bb.z; o.w = acc[i][3] + bb.w;
        *(float4*)&C[(size_t)row * N + c] = o;
    }
}

// ---------------- launch 4: prep (bcomb + logW pack + Wh copy) ----------------
// blocks [0,8): bcomb; [8,16008): logW split+pack; [16008,20104): copy Wh -> Wbig tail
__global__ void __launch_bounds__(256) k_prep(const float* __restrict__ red_b,
                                              const float* __restrict__ Wx,
                                              const float* __restrict__ bl,
                                              const float* __restrict__ logW,
                                              const float* __restrict__ Wh) {
    int blk = blockIdx.x;
    if (blk < 8) {
        int col = blk * 256 + threadIdx.x;
        float acc = bl[col];
        for (int k = 0; k < 256; k++) acc += red_b[k] * Wx[(size_t)k * 2048 + col];
        g_bcomb[col] = acc;
        return;
    }
    if (blk < 16008) {
        int idx = blk - 8;
        __shared__ float tile[32][33];
        int v0 = (idx % 1000) * 32, k0 = (idx / 1000) * 32;
        int tv = threadIdx.x & 31, tr = threadIdx.x >> 5;
        for (int kk = tr; kk < 32; kk += 8)
            tile[kk][tv] = logW[(size_t)(k0 + kk) * Vv + v0 + tv];
        __syncthreads();
        __nv_bfloat16* Wb = (__nv_bfloat16*)g_Wpk;
        for (int vv = tr; vv < 32; vv += 8) {
            float w = tile[tv][vv];
            __nv_bfloat16 hi, lo;
            bf16split(w, &hi, &lo);
            int v = v0 + vv, k = k0 + tv;
            int j = k >> 1;                       // u32 index in [0,256)
            int kt = j >> 3, qc = j & 3;
            int word_hi = (j & 4) >> 2;           // 0 or 1
            size_t e = ((size_t)v * 32 + kt) * 4 + qc;   // uint4 index
            size_t b8 = e * 8;                    // bf16 index of entry start
            Wb[b8 + word_hi * 2 + (k & 1)]     = hi;   // words 0,1: hi pair
            Wb[b8 + 4 + word_hi * 2 + (k & 1)] = lo;   // words 2,3: lo pair
        }
        return;
    }
    {
        int idx = (blk - 16008) * 256 + threadIdx.x;   // 1048576 elements
        g_Wbig[768 * 2048 + idx] = Wh[idx];
    }
}

// ---------------- mma helper ----------------
__device__ __forceinline__ void mma16816(float* c, const uint32_t* a, const uint32_t* b) {
    asm volatile(
        "mma.sync.aligned.m16n8k16.row.col.f32.bf16.bf16.f32 "
        "{%0,%1,%2,%3}, {%4,%5,%6,%7}, {%8,%9}, {%0,%1,%2,%3};"
        : "+f"(c[0]), "+f"(c[1]), "+f"(c[2]), "+f"(c[3])
        : "r"(a[0]), "r"(a[1]), "r"(a[2]), "r"(a[3]), "r"(b[0]), "r"(b[1]));
}

// ---------------- launch 5: persistent step kernel ----------------
__global__ void __launch_bounds__(NTHR) k_step(const int* __restrict__ trg,
                                               const int* __restrict__ ext,
                                               const float* __restrict__ mask,
                                               const float* __restrict__ emb,
                                               const float* __restrict__ catW,
                                               const float* __restrict__ catb,
                                               const float* __restrict__ logb,
                                               float* __restrict__ out) {
    __shared__ float sbuf[2560];
    int cta = blockIdx.x, tid = threadIdx.x;
    int wid = tid >> 5, lane = tid & 31;
    int flat = cta * NTHR + tid;
    int gwarp = cta * 8 + wid;
    int qr = lane >> 2, qc = lane & 3;

    for (int t = 0; t < Tt; t++) {
        // ---- P0: gates partials [e|ctx|h] @ Wbig  (fp32, 128 CTAs) ----
        if (cta < 128) {
            float (*X)[320] = (float(*)[320])sbuf;
            int cc = cta & 7, bg = (cta >> 3) & 3, kz = cta >> 5;
            int b0 = bg * 8, kbase = kz * 320;
            for (int idx = tid; idx < 8 * 320; idx += NTHR) {
                int bb = idx / 320, kl = idx - bb * 320, k = kbase + kl, b = b0 + bb;
                float v;
                if (k < 256)      v = emb[(size_t)trg[b * Tt + t] * 256 + k];
                else if (k < 768) v = g_ctx[b * 512 + k - 256];
                else              v = g_h[b * 512 + k - 768];
                X[bb][kl] = v;
            }
            __syncthreads();
            int col = cc * 256 + tid;
            float acc[8] = {};
            const float* W = g_Wbig + (size_t)kbase * 2048 + col;
            for (int kl = 0; kl < 320; kl += 4) {
                float w0 = W[0], w1 = W[2048], w2 = W[4096], w3 = W[6144];
                W += 4 * 2048;
#pragma unroll
                for (int bb = 0; bb < 8; bb++) {
                    float4 s4 = *(const float4*)&X[bb][kl];
                    acc[bb] += s4.x * w0 + s4.y * w1 + s4.z * w2 + s4.w * w3;
                }
            }
#pragma unroll
            for (int bb = 0; bb < 8; bb++)
                g_gpart[(size_t)(kz * 32 + b0 + bb) * 2048 + col] = acc[bb];
            __syncthreads();
        }
        gbar();

        // ---- P1: gate reduce + LSTM cell; CTAs 96-127 reset prev-step copy slots ----
        if (flat < 16384) {
            int b = flat >> 9, j = flat & 511;
            float gi = g_bcomb[j], gf = g_bcomb[512 + j], gg = g_bcomb[1024 + j], go = g_bcomb[1536 + j];
#pragma unroll
            for (int p = 0; p < 4; p++) {
                const float* gp = g_gpart + (size_t)(p * 32 + b) * 2048;
                gi += gp[j]; gf += gp[512 + j]; gg += gp[1024 + j]; go += gp[1536 + j];
            }
            float c = g_c[flat];
            float si = 1.f / (1.f + __expf(-gi));
            float sf = 1.f / (1.f + __expf(-gf));
            float so = 1.f / (1.f + __expf(-go));
            c = sf * c + si * tanhf(gg);
            float h = so * tanhf(c);
            g_c[flat] = c;
            g_h[flat] = h;
        } else if (cta >= 96 && cta < 128) {
            int idx = (cta - 96) * 256 + tid;     // 8192 touched slots from prev step
            int b = idx >> 8;
            g_copy[(size_t)b * VEXT + ext[idx]] = -NEGC;
        }
        gbar();

        // ---- P2: energy ----
        for (int wj = gwarp; wj < 8192; wj += NCTA * 8) {
            int b = wj >> 8;
            const float4* h4 = (const float4*)(g_h + b * 512);
            const float4* m4 = (const float4*)(g_mem + (size_t)wj * 512);
            float acc = 0.f;
#pragma unroll
            for (int i = 0; i < 4; i++) {
                float4 a = m4[lane + 32 * i];
                float4 x = h4[lane + 32 * i];
                acc += a.x * x.x + a.y * x.y + a.z * x.z + a.w * x.w;
            }
#pragma unroll
            for (int o = 16; o; o >>= 1) acc += __shfl_xor_sync(0xffffffffu, acc, o);
            if (!lane) g_energy[wj] = acc - NEGC * (1.f - mask[wj]);
        }
        gbar();

        // ---- P3: softmax + scatter (32 CTAs) ----
        if (cta < 32) {
            int b = cta;
            float* sr = sbuf;
            float e = g_energy[b * 256 + tid];
            float m = e;
#pragma unroll
            for (int o = 16; o; o >>= 1) m = fmaxf(m, __shfl_xor_sync(0xffffffffu, m, o));
            if (!lane) sr[wid] = m;
            __syncthreads();
            if (tid < 8) {
                float mm = sr[tid];
#pragma unroll
                for (int o = 4; o; o >>= 1) mm = fmaxf(mm, __shfl_xor_sync(0xffu, mm, o));
                if (!tid) sr[8] = mm;
            }
            __syncthreads();
            float mx = sr[8];
            float pexp = __expf(e - mx);
            float ssum = pexp;
#pragma unroll
            for (int o = 16; o; o >>= 1) ssum += __shfl_xor_sync(0xffffffffu, ssum, o);
            __syncthreads();
            if (!lane) sr[wid] = ssum;
            __syncthreads();
            if (tid < 8) {
                float s2 = sr[tid];
#pragma unroll
                for (int o = 4; o; o >>= 1) s2 += __shfl_xor_sync(0xffu, s2, o);
                if (!tid) sr[9] = s2;
            }
            __syncthreads();
            g_attnw[b * 256 + tid] = pexp / sr[9];
            float* addr = &g_copy[(size_t)b * VEXT + ext[b * 256 + tid]];
            if (e >= 0.f) atomicMax((int*)addr, __float_as_int(e));
            else          atomicMin((unsigned int*)addr, __float_as_uint(e));
            __syncthreads();
        }
        gbar();

        // ---- P4: ctx = attn @ memories ----
        if (flat < 16384) {
            int b = flat >> 9, hd = flat & 511;
            const float* aw = g_attnw + b * 256;
            const float* mb = g_mem + (size_t)b * Ss * Hh + hd;
            float a0 = 0.f, a1 = 0.f;
#pragma unroll 8
            for (int s = 0; s < 256; s += 2) {
                a0 += aw[s] * mb[(size_t)s * 512];
                a1 += aw[s + 1] * mb[(size_t)(s + 1) * 512];
            }
            g_ctx[flat] = a0 + a1;
        }
        gbar();

        // ---- P5: cat partials (32 CTAs) ----
        if (cta < 32) {
            float (*C)[256] = (float(*)[256])sbuf;
            int cc = cta & 1, bg = (cta >> 1) & 3, kz = cta >> 3;
            int b0 = bg * 8, kbase = kz * 256;
            for (int idx = tid; idx < 8 * 256; idx += NTHR) {
                int bb = idx >> 8, kl = idx & 255, k = kbase + kl, b = b0 + bb;
                C[bb][kl] = (k < 512) ? g_h[b * 512 + k] : g_ctx[b * 512 + k - 512];
            }
            __syncthreads();
            int col = cc * 256 + tid;
            float acc[8] = {};
            const float* W = catW + (size_t)kbase * 512 + col;
            for (int kl = 0; kl < 256; kl += 4) {
                float w0 = W[0], w1 = W[512], w2 = W[1024], w3 = W[1536];
                W += 4 * 512;
#pragma unroll
                for (int bb = 0; bb < 8; bb++) {
                    float4 s4 = *(const float4*)&C[bb][kl];
                    acc[bb] += s4.x * w0 + s4.y * w1 + s4.z * w2 + s4.w * w3;
                }
            }
#pragma unroll
            for (int bb = 0; bb < 8; bb++)
                g_cpart[(size_t)(kz * 32 + b0 + bb) * 512 + col] = acc[bb];
            __syncthreads();
        }
        gbar();

        // ---- P6: cat reduce + tanh + bf16 split ----
        if (flat < 16384) {
            int b = flat >> 9, col = flat & 511;
            float acc = catb[col];
#pragma unroll
            for (int p = 0; p < 4; p++) acc += g_cpart[(size_t)(p * 32 + b) * 512 + col];
            float s = tanhf(acc);
            __nv_bfloat16 hi, lo;
            bf16split(s, &hi, &lo);
            g_shi[flat] = hi;
            g_slo[flat] = lo;
        }
        gbar();

        // ---- P7: logit mma (125 CTAs, packed-uint4 B loads) + OOV tail ----
        if (cta < 125) {
            int n0 = cta * 256 + wid * 32;
            float acc[2][4][4];
#pragma unroll
            for (int mt = 0; mt < 2; mt++)
#pragma unroll
                for (int nt = 0; nt < 4; nt++)
#pragma unroll
                    for (int i = 0; i < 4; i++) acc[mt][nt][i] = 0.f;
            const uint32_t* shi = (const uint32_t*)g_shi;
            const uint32_t* slo = (const uint32_t*)g_slo;
#pragma unroll 4
            for (int kt = 0; kt < 32; kt++) {
                int kw = kt * 8 + qc;
                uint32_t ahi[2][4], alo[2][4];
#pragma unroll
                for (int mt = 0; mt < 2; mt++) {
                    int r0 = mt * 16 + qr;
                    ahi[mt][0] = shi[r0 * 256 + kw];
                    ahi[mt][1] = shi[(r0 + 8) * 256 + kw];
                    ahi[mt][2] = shi[r0 * 256 + kw + 4];
                    ahi[mt][3] = shi[(r0 + 8) * 256 + kw + 4];
                    alo[mt][0] = slo[r0 * 256 + kw];
                    alo[mt][1] = slo[(r0 + 8) * 256 + kw];
                    alo[mt][2] = slo[r0 * 256 + kw + 4];
                    alo[mt][3] = slo[(r0 + 8) * 256 + kw + 4];
                }
#pragma unroll
                for (int nt = 0; nt < 4; nt++) {
                    uint4 w = g_Wpk[((size_t)(n0 + nt * 8 + qr) * 32 + kt) * 4 + qc];
                    uint32_t bhi[2] = { w.x, w.y };
                    uint32_t blo[2] = { w.z, w.w };
#pragma unroll
                    for (int mt = 0; mt < 2; mt++) {
                        mma16816(acc[mt][nt], ahi[mt], bhi);
                        mma16816(acc[mt][nt], ahi[mt], blo);
                        mma16816(acc[mt][nt], alo[mt], bhi);
                    }
                }
            }
#pragma unroll
            for (int mt = 0; mt < 2; mt++) {
#pragma unroll
                for (int nt = 0; nt < 4; nt++) {
                    int v = n0 + nt * 8 + qc * 2;
                    float lb0 = logb[v], lb1 = logb[v + 1];
#pragma unroll
                    for (int half = 0; half < 2; half++) {
                        int b = mt * 16 + qr + half * 8;
                        const float* crow = g_copy + (size_t)b * VEXT;
                        float c0 = crow[v], c1 = crow[v + 1];
                        c0 = (c0 <= -5e11f) ? 0.f : c0;
                        c1 = (c1 <= -5e11f) ? 0.f : c1;
                        float2 o;
                        o.x = acc[mt][nt][half * 2 + 0] + lb0 + c0;
                        o.y = acc[mt][nt][half * 2 + 1] + lb1 + c1;
                        *(float2*)&out[(size_t)b * Tt * VEXT + (size_t)t * VEXT + v] = o;
                    }
                }
            }
        } else {
            int oidx = flat - 125 * 256;
            if (oidx >= 0 && oidx < Bz * OOV) {
                int b = oidx / OOV, j = oidx - b * OOV;
                float cv = g_copy[(size_t)b * VEXT + Vv + j];
                cv = (cv <= -5e11f) ? 0.f : cv;
                out[(size_t)b * Tt * VEXT + (size_t)t * VEXT + Vv + j] = cv;
            }
        }
        gbar();
    }
}

// ---------------- launcher ----------------
extern "C" void kernel_launch(void* const* d_in, const int* in_sizes, int n_in,
                              void* d_out, int out_size) {
    const int*   trg   = (const int*)d_in[0];
    const int*   ext   = (const int*)d_in[1];
    const float* encO  = (const float*)d_in[2];
    const float* mask  = (const float*)d_in[3];
    const float* h0    = (const float*)d_in[4];
    const float* c0    = (const float*)d_in[5];
    const float* emb   = (const float*)d_in[6];
    const float* encW  = (const float*)d_in[7];
    const float* encb  = (const float*)d_in[8];
    const float* redW  = (const float*)d_in[9];
    const float* redb  = (const float*)d_in[10];
    const float* Wx    = (const float*)d_in[11];
    const float* Wh    = (const float*)d_in[12];
    const float* bl    = (const float*)d_in[13];
    const float* catW  = (const float*)d_in[14];
    const float* catb  = (const float*)d_in[15];
    const float* logW  = (const float*)d_in[16];
    const float* logb  = (const float*)d_in[17];
    float* out = (float*)d_out;

    k_init<<<64, 256>>>(h0, c0);                                                      // 0
    k_resetfull<<<(Bz * VEXT + 255) / 256, 256>>>();                                  // 1
    k_gemm<<<dim3(512 / 64, 8192 / 64), 256>>>(encO, encW, encb, 8192, 512, 512, 0);  // 2
    k_gemm<<<dim3(2048 / 64, 768 / 64), 256>>>(redW, Wx, nullptr, 768, 256, 2048, 1); // 3
    k_prep<<<20104, 256>>>(redb, Wx, bl, logW, Wh);                                   // 4
    k_step<<<NCTA, NTHR>>>(trg, ext, mask, emb, catW, catb, logb, out);               // 5
}

// round 16
// speedup vs baseline: 1.1424x; 1.1424x over previous
#include <cuda_runtime.h>
#include <cuda_bf16.h>
#include <math.h>
#include <stdint.h>

#define Bz   32
#define Tt   32
#define Ss   256
#define Vv   32000
#define Ee   256
#define Hh   512
#define OOV  50
#define VEXT 32050
#define NEGC 1.0e12f
#define NCTA 148
#define NTHR 256

// ---------------- device state ----------------
__device__ float g_mem[Bz * Ss * Hh];        // memories [B,S,H] (16 MB)
__device__ float g_h[Bz * Hh];
__device__ float g_c[Bz * Hh];
__device__ float g_ctx[Bz * Hh];
__device__ float g_copy[Bz * VEXT];
__device__ float g_Wbig[1280 * 2048];        // [red_W@Wx ; Wh]
__device__ float g_bcomb[2048];
__device__ float g_gpart[4 * Bz * 2048];
__device__ float g_cpart[4 * Bz * 512];
__device__ float g_energy[Bz * Ss];
__device__ float g_attnw[Bz * Ss];
// logit weight split, [V, K] K-major (read-only -> L1-cacheable)
__device__ __align__(16) __nv_bfloat16 g_WhiT[(size_t)Vv * Hh];
__device__ __align__(16) __nv_bfloat16 g_WloT[(size_t)Vv * Hh];
__device__ __align__(16) __nv_bfloat16 g_shi[Bz * Hh];
__device__ __align__(16) __nv_bfloat16 g_slo[Bz * Hh];
__device__ unsigned int g_bar_cnt;

// ---------------- global barrier: release-atomic + acquire-spin, NO L1 flush ----------------
__device__ __forceinline__ void gbar(unsigned int& target) {
    __syncthreads();
    if (threadIdx.x == 0) {
        unsigned int* cnt = &g_bar_cnt;
        asm volatile("red.add.release.gpu.u32 [%0], 1;" :: "l"(cnt) : "memory");
        target += NCTA;
        unsigned int v;
        do {
            asm volatile("ld.acquire.gpu.u32 %0, [%1];" : "=r"(v) : "l"(cnt) : "memory");
        } while (v < target);
    }
    __syncthreads();
}

__device__ __forceinline__ void bf16split(float v, __nv_bfloat16* hi, __nv_bfloat16* lo) {
    __nv_bfloat16 h = __float2bfloat16(v);
    *hi = h;
    *lo = __float2bfloat16(v - __bfloat162float(h));
}

// ---------------- launch 0: init ----------------
__global__ void k_init(const float* __restrict__ h0, const float* __restrict__ c0) {
    int idx = blockIdx.x * 256 + threadIdx.x;     // 16384
    g_h[idx] = h0[idx];
    g_c[idx] = c0[idx];
    g_ctx[idx] = 0.f;
    if (idx == 0) g_bar_cnt = 0;
}

// ---------------- launch 1: reset copy buffer ----------------
__global__ void k_resetfull() {
    int idx = blockIdx.x * 256 + threadIdx.x;
    if (idx < Bz * VEXT) g_copy[idx] = -NEGC;
}

// ---------------- launches 2,3: tiled GEMM (setup) ----------------
__global__ void __launch_bounds__(256) k_gemm(const float* __restrict__ A,
                                              const float* __restrict__ B,
                                              const float* __restrict__ bias,
                                              int M, int K, int N, int dst) {
    float* C = dst ? g_Wbig : g_mem;
    __shared__ float As[16][65];
    __shared__ float Bs[16][64];
    int tx = threadIdx.x & 15, ty = threadIdx.x >> 4;
    int row0 = blockIdx.y * 64, col0 = blockIdx.x * 64;
    int lrow = threadIdx.x >> 2;
    int kq   = (threadIdx.x & 3) * 4;
    int bkk  = threadIdx.x >> 4;
    int bcq  = (threadIdx.x & 15) * 4;
    float acc[4][4] = {};
    for (int k0 = 0; k0 < K; k0 += 16) {
        float4 av = *(const float4*)&A[(size_t)(row0 + lrow) * K + k0 + kq];
        float4 bv = *(const float4*)&B[(size_t)(k0 + bkk) * N + col0 + bcq];
        As[kq + 0][lrow] = av.x; As[kq + 1][lrow] = av.y;
        As[kq + 2][lrow] = av.z; As[kq + 3][lrow] = av.w;
        *(float4*)&Bs[bkk][bcq] = bv;
        __syncthreads();
#pragma unroll
        for (int kk = 0; kk < 16; kk++) {
            float a0 = As[kk][ty * 4 + 0], a1 = As[kk][ty * 4 + 1];
            float a2 = As[kk][ty * 4 + 2], a3 = As[kk][ty * 4 + 3];
            float4 b4 = *(const float4*)&Bs[kk][tx * 4];
            acc[0][0] += a0 * b4.x; acc[0][1] += a0 * b4.y; acc[0][2] += a0 * b4.z; acc[0][3] += a0 * b4.w;
            acc[1][0] += a1 * b4.x; acc[1][1] += a1 * b4.y; acc[1][2] += a1 * b4.z; acc[1][3] += a1 * b4.w;
            acc[2][0] += a2 * b4.x; acc[2][1] += a2 * b4.y; acc[2][2] += a2 * b4.z; acc[2][3] += a2 * b4.w;
            acc[3][0] += a3 * b4.x; acc[3][1] += a3 * b4.y; acc[3][2] += a3 * b4.z; acc[3][3] += a3 * b4.w;
        }
        __syncthreads();
    }
    int c = col0 + tx * 4;
    float4 bb = bias ? *(const float4*)&bias[c] : make_float4(0.f, 0.f, 0.f, 0.f);
#pragma unroll
    for (int i = 0; i < 4; i++) {
        int row = row0 + ty * 4 + i;
        float4 o;
        o.x = acc[i][0] + bb.x; o.y = acc[i][1] + bb.y;
        o.z = acc[i][2] + bb.z; o.w = acc[i][3] + bb.w;
        *(float4*)&C[(size_t)row * N + c] = o;
    }
}

// ---------------- launch 4: prep (bcomb + logW split + Wh copy) ----------------
__global__ void __launch_bounds__(256) k_prep(const float* __restrict__ red_b,
                                              const float* __restrict__ Wx,
                                              const float* __restrict__ bl,
                                              const float* __restrict__ logW,
                                              const float* __restrict__ Wh) {
    int blk = blockIdx.x;
    if (blk < 8) {
        int col = blk * 256 + threadIdx.x;
        float acc = bl[col];
        for (int k = 0; k < 256; k++) acc += red_b[k] * Wx[(size_t)k * 2048 + col];
        g_bcomb[col] = acc;
        return;
    }
    if (blk < 16008) {
        int idx = blk - 8;
        __shared__ float tile[32][33];
        int v0 = (idx % 1000) * 32, k0 = (idx / 1000) * 32;
        int tv = threadIdx.x & 31, tr = threadIdx.x >> 5;
        for (int kk = tr; kk < 32; kk += 8)
            tile[kk][tv] = logW[(size_t)(k0 + kk) * Vv + v0 + tv];
        __syncthreads();
        for (int vv = tr; vv < 32; vv += 8) {
            float w = tile[tv][vv];
            __nv_bfloat16 hi, lo;
            bf16split(w, &hi, &lo);
            size_t o = (size_t)(v0 + vv) * Hh + k0 + tv;
            g_WhiT[o] = hi;
            g_WloT[o] = lo;
        }
        return;
    }
    {
        int idx = (blk - 16008) * 256 + threadIdx.x;   // 1048576 elements
        g_Wbig[768 * 2048 + idx] = Wh[idx];
    }
}

// ---------------- mma helper ----------------
__device__ __forceinline__ void mma16816(float* c, const uint32_t* a, const uint32_t* b) {
    asm volatile(
        "mma.sync.aligned.m16n8k16.row.col.f32.bf16.bf16.f32 "
        "{%0,%1,%2,%3}, {%4,%5,%6,%7}, {%8,%9}, {%0,%1,%2,%3};"
        : "+f"(c[0]), "+f"(c[1]), "+f"(c[2]), "+f"(c[3])
        : "r"(a[0]), "r"(a[1]), "r"(a[2]), "r"(a[3]), "r"(b[0]), "r"(b[1]));
}

// ---------------- launch 5: persistent step kernel ----------------
__global__ void __launch_bounds__(NTHR) k_step(const int* __restrict__ trg,
                                               const int* __restrict__ ext,
                                               const float* __restrict__ mask,
                                               const float* __restrict__ emb,
                                               const float* __restrict__ catW,
                                               const float* __restrict__ catb,
                                               const float* __restrict__ logb,
                                               float* __restrict__ out) {
    __shared__ float sbuf[2560];
    int cta = blockIdx.x, tid = threadIdx.x;
    int wid = tid >> 5, lane = tid & 31;
    int flat = cta * NTHR + tid;
    int gwarp = cta * 8 + wid;
    int qr = lane >> 2, qc = lane & 3;
    unsigned int bt = 0;                 // barrier target (monotonic counter)

    for (int t = 0; t < Tt; t++) {
        // ---- P0: gates partials [e|ctx|h] @ Wbig  (fp32, 128 CTAs) ----
        if (cta < 128) {
            float (*X)[320] = (float(*)[320])sbuf;
            int cc = cta & 7, bg = (cta >> 3) & 3, kz = cta >> 5;
            int b0 = bg * 8, kbase = kz * 320;
            for (int idx = tid; idx < 8 * 320; idx += NTHR) {
                int bb = idx / 320, kl = idx - bb * 320, k = kbase + kl, b = b0 + bb;
                float v;
                if (k < 256)      v = emb[(size_t)trg[b * Tt + t] * 256 + k];
                else if (k < 768) v = __ldcg(&g_ctx[b * 512 + k - 256]);
                else              v = __ldcg(&g_h[b * 512 + k - 768]);
                X[bb][kl] = v;
            }
            __syncthreads();
            int col = cc * 256 + tid;
            float acc[8] = {};
            const float* W = g_Wbig + (size_t)kbase * 2048 + col;
            for (int kl = 0; kl < 320; kl += 4) {
                float w0 = W[0], w1 = W[2048], w2 = W[4096], w3 = W[6144];
                W += 4 * 2048;
#pragma unroll
                for (int bb = 0; bb < 8; bb++) {
                    float4 s4 = *(const float4*)&X[bb][kl];
                    acc[bb] += s4.x * w0 + s4.y * w1 + s4.z * w2 + s4.w * w3;
                }
            }
#pragma unroll
            for (int bb = 0; bb < 8; bb++)
                g_gpart[(size_t)(kz * 32 + b0 + bb) * 2048 + col] = acc[bb];
            __syncthreads();
        }
        gbar(bt);

        // ---- P1: gate reduce + LSTM cell; CTAs 96-127 reset prev-step copy slots ----
        if (flat < 16384) {
            int b = flat >> 9, j = flat & 511;
            float gi = g_bcomb[j], gf = g_bcomb[512 + j], gg = g_bcomb[1024 + j], go = g_bcomb[1536 + j];
#pragma unroll
            for (int p = 0; p < 4; p++) {
                const float* gp = g_gpart + (size_t)(p * 32 + b) * 2048;
                gi += __ldcg(&gp[j]);
                gf += __ldcg(&gp[512 + j]);
                gg += __ldcg(&gp[1024 + j]);
                go += __ldcg(&gp[1536 + j]);
            }
            float c = g_c[flat];
            float si = 1.f / (1.f + __expf(-gi));
            float sf = 1.f / (1.f + __expf(-gf));
            float so = 1.f / (1.f + __expf(-go));
            c = sf * c + si * tanhf(gg);
            float h = so * tanhf(c);
            g_c[flat] = c;
            g_h[flat] = h;
        } else if (cta >= 96 && cta < 128) {
            int idx = (cta - 96) * 256 + tid;     // 8192 touched slots from prev step
            int b = idx >> 8;
            g_copy[(size_t)b * VEXT + ext[idx]] = -NEGC;
        }
        gbar(bt);

        // ---- P2: energy ----
        for (int wj = gwarp; wj < 8192; wj += NCTA * 8) {
            int b = wj >> 8;
            const float4* h4 = (const float4*)(g_h + b * 512);
            const float4* m4 = (const float4*)(g_mem + (size_t)wj * 512);
            float acc = 0.f;
#pragma unroll
            for (int i = 0; i < 4; i++) {
                float4 a = m4[lane + 32 * i];
                float4 x = __ldcg(&h4[lane + 32 * i]);
                acc += a.x * x.x + a.y * x.y + a.z * x.z + a.w * x.w;
            }
#pragma unroll
            for (int o = 16; o; o >>= 1) acc += __shfl_xor_sync(0xffffffffu, acc, o);
            if (!lane) g_energy[wj] = acc - NEGC * (1.f - mask[wj]);
        }
        gbar(bt);

        // ---- P3: softmax + scatter (32 CTAs) ----
        if (cta < 32) {
            int b = cta;
            float* sr = sbuf;
            float e = __ldcg(&g_energy[b * 256 + tid]);
            float m = e;
#pragma unroll
            for (int o = 16; o; o >>= 1) m = fmaxf(m, __shfl_xor_sync(0xffffffffu, m, o));
            if (!lane) sr[wid] = m;
            __syncthreads();
            if (tid < 8) {
                float mm = sr[tid];
#pragma unroll
                for (int o = 4; o; o >>= 1) mm = fmaxf(mm, __shfl_xor_sync(0xffu, mm, o));
                if (!tid) sr[8] = mm;
            }
            __syncthreads();
            float mx = sr[8];
            float pexp = __expf(e - mx);
            float ssum = pexp;
#pragma unroll
            for (int o = 16; o; o >>= 1) ssum += __shfl_xor_sync(0xffffffffu, ssum, o);
            __syncthreads();
            if (!lane) sr[wid] = ssum;
            __syncthreads();
            if (tid < 8) {
                float s2 = sr[tid];
#pragma unroll
                for (int o = 4; o; o >>= 1) s2 += __shfl_xor_sync(0xffu, s2, o);
                if (!tid) sr[9] = s2;
            }
            __syncthreads();
            g_attnw[b * 256 + tid] = pexp / sr[9];
            float* addr = &g_copy[(size_t)b * VEXT + ext[b * 256 + tid]];
            if (e >= 0.f) atomicMax((int*)addr, __float_as_int(e));
            else          atomicMin((unsigned int*)addr, __float_as_uint(e));
            __syncthreads();
        }
        gbar(bt);

        // ---- P4: ctx = attn @ memories ----
        if (flat < 16384) {
            int b = flat >> 9, hd = flat & 511;
            const float* aw = g_attnw + b * 256;
            const float* mb = g_mem + (size_t)b * Ss * Hh + hd;
            float a0 = 0.f, a1 = 0.f;
#pragma unroll 8
            for (int s = 0; s < 256; s += 2) {
                a0 += __ldcg(&aw[s]) * mb[(size_t)s * 512];
                a1 += __ldcg(&aw[s + 1]) * mb[(size_t)(s + 1) * 512];
            }
            g_ctx[flat] = a0 + a1;
        }
        gbar(bt);

        // ---- P5: cat partials (32 CTAs) ----
        if (cta < 32) {
            float (*C)[256] = (float(*)[256])sbuf;
            int cc = cta & 1, bg = (cta >> 1) & 3, kz = cta >> 3;
            int b0 = bg * 8, kbase = kz * 256;
            for (int idx = tid; idx < 8 * 256; idx += NTHR) {
                int bb = idx >> 8, kl = idx & 255, k = kbase + kl, b = b0 + bb;
                C[bb][kl] = (k < 512) ? __ldcg(&g_h[b * 512 + k])
                                      : __ldcg(&g_ctx[b * 512 + k - 512]);
            }
            __syncthreads();
            int col = cc * 256 + tid;
            float acc[8] = {};
            const float* W = catW + (size_t)kbase * 512 + col;
            for (int kl = 0; kl < 256; kl += 4) {
                float w0 = W[0], w1 = W[512], w2 = W[1024], w3 = W[1536];
                W += 4 * 512;
#pragma unroll
                for (int bb = 0; bb < 8; bb++) {
                    float4 s4 = *(const float4*)&C[bb][kl];
                    acc[bb] += s4.x * w0 + s4.y * w1 + s4.z * w2 + s4.w * w3;
                }
            }
#pragma unroll
            for (int bb = 0; bb < 8; bb++)
                g_cpart[(size_t)(kz * 32 + b0 + bb) * 512 + col] = acc[bb];
            __syncthreads();
        }
        gbar(bt);

        // ---- P6: cat reduce + tanh + bf16 split ----
        if (flat < 16384) {
            int b = flat >> 9, col = flat & 511;
            float acc = catb[col];
#pragma unroll
            for (int p = 0; p < 4; p++) acc += __ldcg(&g_cpart[(size_t)(p * 32 + b) * 512 + col]);
            float s = tanhf(acc);
            __nv_bfloat16 hi, lo;
            bf16split(s, &hi, &lo);
            g_shi[flat] = hi;
            g_slo[flat] = lo;
        }
        gbar(bt);

        // ---- P7: logit mma (125 CTAs) + OOV tail ----
        if (cta < 125) {
            int n0 = cta * 256 + wid * 32;
            float acc[2][4][4];
#pragma unroll
            for (int mt = 0; mt < 2; mt++)
#pragma unroll
                for (int nt = 0; nt < 4; nt++)
#pragma unroll
                    for (int i = 0; i < 4; i++) acc[mt][nt][i] = 0.f;
            const uint32_t* shi = (const uint32_t*)g_shi;
            const uint32_t* slo = (const uint32_t*)g_slo;
            const uint32_t* WhiT = (const uint32_t*)g_WhiT;
            const uint32_t* WloT = (const uint32_t*)g_WloT;
#pragma unroll 4
            for (int kt = 0; kt < 32; kt++) {
                int kw = kt * 8 + qc;
                uint32_t ahi[2][4], alo[2][4];
#pragma unroll
                for (int mt = 0; mt < 2; mt++) {
                    int r0 = mt * 16 + qr;
                    ahi[mt][0] = __ldcg(&shi[r0 * 256 + kw]);
                    ahi[mt][1] = __ldcg(&shi[(r0 + 8) * 256 + kw]);
                    ahi[mt][2] = __ldcg(&shi[r0 * 256 + kw + 4]);
                    ahi[mt][3] = __ldcg(&shi[(r0 + 8) * 256 + kw + 4]);
                    alo[mt][0] = __ldcg(&slo[r0 * 256 + kw]);
                    alo[mt][1] = __ldcg(&slo[(r0 + 8) * 256 + kw]);
                    alo[mt][2] = __ldcg(&slo[r0 * 256 + kw + 4]);
                    alo[mt][3] = __ldcg(&slo[(r0 + 8) * 256 + kw + 4]);
                }
#pragma unroll
                for (int nt = 0; nt < 4; nt++) {
                    size_t nrow = (size_t)(n0 + nt * 8 + qr) * 256;
                    uint32_t bhi[2], blo[2];
                    bhi[0] = WhiT[nrow + kw];
                    bhi[1] = WhiT[nrow + kw + 4];
                    blo[0] = WloT[nrow + kw];
                    blo[1] = WloT[nrow + kw + 4];
#pragma unroll
                    for (int mt = 0; mt < 2; mt++) {
                        mma16816(acc[mt][nt], ahi[mt], bhi);
                        mma16816(acc[mt][nt], ahi[mt], blo);
                        mma16816(acc[mt][nt], alo[mt], bhi);
                    }
                }
            }
#pragma unroll
            for (int mt = 0; mt < 2; mt++) {
#pragma unroll
                for (int nt = 0; nt < 4; nt++) {
                    int v = n0 + nt * 8 + qc * 2;
                    float lb0 = logb[v], lb1 = logb[v + 1];
#pragma unroll
                    for (int half = 0; half < 2; half++) {
                        int b = mt * 16 + qr + half * 8;
                        const float* crow = g_copy + (size_t)b * VEXT;
                        float c0 = __ldcg(&crow[v]), c1 = __ldcg(&crow[v + 1]);
                        c0 = (c0 <= -5e11f) ? 0.f : c0;
                        c1 = (c1 <= -5e11f) ? 0.f : c1;
                        float2 o;
                        o.x = acc[mt][nt][half * 2 + 0] + lb0 + c0;
                        o.y = acc[mt][nt][half * 2 + 1] + lb1 + c1;
                        *(float2*)&out[(size_t)b * Tt * VEXT + (size_t)t * VEXT + v] = o;
                    }
                }
            }
        } else {
            int oidx = flat - 125 * 256;
            if (oidx >= 0 && oidx < Bz * OOV) {
                int b = oidx / OOV, j = oidx - b * OOV;
                float cv = __ldcg(&g_copy[(size_t)b * VEXT + Vv + j]);
                cv = (cv <= -5e11f) ? 0.f : cv;
                out[(size_t)b * Tt * VEXT + (size_t)t * VEXT + Vv + j] = cv;
            }
        }
        gbar(bt);
    }
}

// ---------------- launcher ----------------
extern "C" void kernel_launch(void* const* d_in, const int* in_sizes, int n_in,
                              void* d_out, int out_size) {
    const int*   trg   = (const int*)d_in[0];
    const int*   ext   = (const int*)d_in[1];
    const float* encO  = (const float*)d_in[2];
    const float* mask  = (const float*)d_in[3];
    const float* h0    = (const float*)d_in[4];
    const float* c0    = (const float*)d_in[5];
    const float* emb   = (const float*)d_in[6];
    const float* encW  = (const float*)d_in[7];
    const float* encb  = (const float*)d_in[8];
    const float* redW  = (const float*)d_in[9];
    const float* redb  = (const float*)d_in[10];
    const float* Wx    = (const float*)d_in[11];
    const float* Wh    = (const float*)d_in[12];
    const float* bl    = (const float*)d_in[13];
    const float* catW  = (const float*)d_in[14];
    const float* catb  = (const float*)d_in[15];
    const float* logW  = (const float*)d_in[16];
    const float* logb  = (const float*)d_in[17];
    float* out = (float*)d_out;

    k_init<<<64, 256>>>(h0, c0);                                                      // 0
    k_resetfull<<<(Bz * VEXT + 255) / 256, 256>>>();                                  // 1
    k_gemm<<<dim3(512 / 64, 8192 / 64), 256>>>(encO, encW, encb, 8192, 512, 512, 0);  // 2
    k_gemm<<<dim3(2048 / 64, 768 / 64), 256>>>(redW, Wx, nullptr, 768, 256, 2048, 1); // 3
    k_prep<<<20104, 256>>>(redb, Wx, bl, logW, Wh);                                   // 4
    k_step<<<NCTA, NTHR>>>(trg, ext, mask, emb, catW, catb, logb, out);               // 5
}

// round 17
// speedup vs baseline: 1.4865x; 1.3012x over previous
#include <cuda_runtime.h>
#include <cuda_bf16.h>
#include <math.h>
#include <stdint.h>

#define Bz   32
#define Tt   32
#define Ss   256
#define Vv   32000
#define Ee   256
#define Hh   512
#define OOV  50
#define VEXT 32050
#define NEGC 1.0e12f
#define NCTA 148
#define NTHR 256

// ---------------- device state ----------------
__device__ float g_mem[Bz * Ss * Hh];        // memories [B,S,H] (16 MB)
__device__ float g_h[Bz * Hh];
__device__ float g_c[Bz * Hh];
__device__ float g_ctx[Bz * Hh];
__device__ float g_copy[Bz * VEXT];
__device__ float g_Wbig[1280 * 2048];        // [red_W@Wx ; Wh]
__device__ float g_bcomb[2048];
__device__ float g_gpart[4 * Bz * 2048];
__device__ float g_cpart[4 * Bz * 512];
__device__ float g_energy[Bz * Ss];
__device__ float g_attnw[Bz * Ss];
// logit weight split, [V, K] K-major
__device__ __align__(16) __nv_bfloat16 g_WhiT[(size_t)Vv * Hh];
__device__ __align__(16) __nv_bfloat16 g_WloT[(size_t)Vv * Hh];
__device__ __align__(16) __nv_bfloat16 g_shi[Bz * Hh];
__device__ __align__(16) __nv_bfloat16 g_slo[Bz * Hh];
__device__ unsigned int g_bar_cnt;
__device__ unsigned int g_bar_gen;

// packed fp32x2 FMA (Blackwell): acc(2xfp32) += a(2xfp32) * b(2xfp32)
#define FMA2(acc, a, b) \
    asm("fma.rn.f32x2 %0, %1, %2, %0;" : "+l"(acc) : "l"(a), "l"(b))
#define PACK2(d, lo, hi) \
    asm("mov.b64 %0, {%1, %2};" : "=l"(d) : "f"(lo), "f"(hi))
#define UNPACK2(lo, hi, s) \
    asm("mov.b64 {%0, %1}, %2;" : "=f"(lo), "=f"(hi) : "l"(s))

// ---------------- global barrier: release-arrive + spin + single fence ----------------
__device__ __forceinline__ void gbar() {
    __syncthreads();
    if (threadIdx.x == 0) {
        volatile unsigned int* vgen = &g_bar_gen;
        unsigned int gen = *vgen;
        unsigned int* cnt = &g_bar_cnt;
        unsigned int arrived;
        asm volatile("atom.add.release.gpu.u32 %0, [%1], 1;"
                     : "=r"(arrived) : "l"(cnt) : "memory");
        if (arrived == NCTA - 1) {
            g_bar_cnt = 0;
            __threadfence();
            *vgen = gen + 1;
        } else {
            while (*vgen == gen) { }
            __threadfence();
        }
    }
    __syncthreads();
}

__device__ __forceinline__ void bf16split(float v, __nv_bfloat16* hi, __nv_bfloat16* lo) {
    __nv_bfloat16 h = __float2bfloat16(v);
    *hi = h;
    *lo = __float2bfloat16(v - __bfloat162float(h));
}

// ---------------- launch 0: init ----------------
__global__ void k_init(const float* __restrict__ h0, const float* __restrict__ c0) {
    int idx = blockIdx.x * 256 + threadIdx.x;     // 16384
    g_h[idx] = h0[idx];
    g_c[idx] = c0[idx];
    g_ctx[idx] = 0.f;
    if (idx == 0) { g_bar_cnt = 0; g_bar_gen = 0; }
}

// ---------------- launch 1: reset copy buffer ----------------
__global__ void k_resetfull() {
    int idx = blockIdx.x * 256 + threadIdx.x;
    if (idx < Bz * VEXT) g_copy[idx] = -NEGC;
}

// ---------------- launches 2,3: tiled GEMM (setup) ----------------
__global__ void __launch_bounds__(256) k_gemm(const float* __restrict__ A,
                                              const float* __restrict__ B,
                                              const float* __restrict__ bias,
                                              int M, int K, int N, int dst) {
    float* C = dst ? g_Wbig : g_mem;
    __shared__ float As[16][65];
    __shared__ float Bs[16][64];
    int tx = threadIdx.x & 15, ty = threadIdx.x >> 4;
    int row0 = blockIdx.y * 64, col0 = blockIdx.x * 64;
    int lrow = threadIdx.x >> 2;
    int kq   = (threadIdx.x & 3) * 4;
    int bkk  = threadIdx.x >> 4;
    int bcq  = (threadIdx.x & 15) * 4;
    float acc[4][4] = {};
    for (int k0 = 0; k0 < K; k0 += 16) {
        float4 av = *(const float4*)&A[(size_t)(row0 + lrow) * K + k0 + kq];
        float4 bv = *(const float4*)&B[(size_t)(k0 + bkk) * N + col0 + bcq];
        As[kq + 0][lrow] = av.x; As[kq + 1][lrow] = av.y;
        As[kq + 2][lrow] = av.z; As[kq + 3][lrow] = av.w;
        *(float4*)&Bs[bkk][bcq] = bv;
        __syncthreads();
#pragma unroll
        for (int kk = 0; kk < 16; kk++) {
            float a0 = As[kk][ty * 4 + 0], a1 = As[kk][ty * 4 + 1];
            float a2 = As[kk][ty * 4 + 2], a3 = As[kk][ty * 4 + 3];
            float4 b4 = *(const float4*)&Bs[kk][tx * 4];
            acc[0][0] += a0 * b4.x; acc[0][1] += a0 * b4.y; acc[0][2] += a0 * b4.z; acc[0][3] += a0 * b4.w;
            acc[1][0] += a1 * b4.x; acc[1][1] += a1 * b4.y; acc[1][2] += a1 * b4.z; acc[1][3] += a1 * b4.w;
            acc[2][0] += a2 * b4.x; acc[2][1] += a2 * b4.y; acc[2][2] += a2 * b4.z; acc[2][3] += a2 * b4.w;
            acc[3][0] += a3 * b4.x; acc[3][1] += a3 * b4.y; acc[3][2] += a3 * b4.z; acc[3][3] += a3 * b4.w;
        }
        __syncthreads();
    }
    int c = col0 + tx * 4;
    float4 bb = bias ? *(const float4*)&bias[c] : make_float4(0.f, 0.f, 0.f, 0.f);
#pragma unroll
    for (int i = 0; i < 4; i++) {
        int row = row0 + ty * 4 + i;
        float4 o;
        o.x = acc[i][0] + bb.x; o.y = acc[i][1] + bb.y;
        o.z = acc[i][2] + bb.z; o.w = acc[i][3] + bb.w;
        *(float4*)&C[(size_t)row * N + c] = o;
    }
}

// ---------------- launch 4: prep (bcomb + logW split + Wh copy) ----------------
__global__ void __launch_bounds__(256) k_prep(const float* __restrict__ red_b,
                                              const float* __restrict__ Wx,
                                              const float* __restrict__ bl,
                                              const float* __restrict__ logW,
                                              const float* __restrict__ Wh) {
    int blk = blockIdx.x;
    if (blk < 8) {
        int col = blk * 256 + threadIdx.x;
        float acc = bl[col];
        for (int k = 0; k < 256; k++) acc += red_b[k] * Wx[(size_t)k * 2048 + col];
        g_bcomb[col] = acc;
        return;
    }
    if (blk < 16008) {
        int idx = blk - 8;
        __shared__ float tile[32][33];
        int v0 = (idx % 1000) * 32, k0 = (idx / 1000) * 32;
        int tv = threadIdx.x & 31, tr = threadIdx.x >> 5;
        for (int kk = tr; kk < 32; kk += 8)
            tile[kk][tv] = logW[(size_t)(k0 + kk) * Vv + v0 + tv];
        __syncthreads();
        for (int vv = tr; vv < 32; vv += 8) {
            float w = tile[tv][vv];
            __nv_bfloat16 hi, lo;
            bf16split(w, &hi, &lo);
            size_t o = (size_t)(v0 + vv) * Hh + k0 + tv;
            g_WhiT[o] = hi;
            g_WloT[o] = lo;
        }
        return;
    }
    {
        int idx = (blk - 16008) * 256 + threadIdx.x;   // 1048576 elements
        g_Wbig[768 * 2048 + idx] = Wh[idx];
    }
}

// ---------------- mma helper ----------------
__device__ __forceinline__ void mma16816(float* c, const uint32_t* a, const uint32_t* b) {
    asm volatile(
        "mma.sync.aligned.m16n8k16.row.col.f32.bf16.bf16.f32 "
        "{%0,%1,%2,%3}, {%4,%5,%6,%7}, {%8,%9}, {%0,%1,%2,%3};"
        : "+f"(c[0]), "+f"(c[1]), "+f"(c[2]), "+f"(c[3])
        : "r"(a[0]), "r"(a[1]), "r"(a[2]), "r"(a[3]), "r"(b[0]), "r"(b[1]));
}

// ---------------- launch 5: persistent step kernel ----------------
__global__ void __launch_bounds__(NTHR) k_step(const int* __restrict__ trg,
                                               const int* __restrict__ ext,
                                               const float* __restrict__ mask,
                                               const float* __restrict__ emb,
                                               const float* __restrict__ catW,
                                               const float* __restrict__ catb,
                                               const float* __restrict__ logb,
                                               float* __restrict__ out) {
    __shared__ float sbuf[2560];
    int cta = blockIdx.x, tid = threadIdx.x;
    int wid = tid >> 5, lane = tid & 31;
    int flat = cta * NTHR + tid;
    int gwarp = cta * 8 + wid;
    int qr = lane >> 2, qc = lane & 3;

    for (int t = 0; t < Tt; t++) {
        // ---- P0: gates partials [e|ctx|h] @ Wbig  (fp32x2, 128 CTAs) ----
        if (cta < 128) {
            float (*X)[320] = (float(*)[320])sbuf;
            int cc = cta & 7, bg = (cta >> 3) & 3, kz = cta >> 5;
            int b0 = bg * 8, kbase = kz * 320;
            for (int idx = tid; idx < 8 * 320; idx += NTHR) {
                int bb = idx / 320, kl = idx - bb * 320, k = kbase + kl, b = b0 + bb;
                float v;
                if (k < 256)      v = emb[(size_t)trg[b * Tt + t] * 256 + k];
                else if (k < 768) v = g_ctx[b * 512 + k - 256];
                else              v = g_h[b * 512 + k - 768];
                X[bb][kl] = v;
            }
            __syncthreads();
            int col = cc * 256 + tid;
            unsigned long long acc2[8] = {};       // packed {even-k sum, odd-k sum}
            const float* W = g_Wbig + (size_t)kbase * 2048 + col;
            for (int kl = 0; kl < 320; kl += 4) {
                float w0 = W[0], w1 = W[2048], w2 = W[4096], w3 = W[6144];
                W += 4 * 2048;
                unsigned long long w01, w23;
                PACK2(w01, w0, w1);
                PACK2(w23, w2, w3);
#pragma unroll
                for (int bb = 0; bb < 8; bb++) {
                    ulonglong2 xv = *(const ulonglong2*)&X[bb][kl];
                    FMA2(acc2[bb], xv.x, w01);
                    FMA2(acc2[bb], xv.y, w23);
                }
            }
#pragma unroll
            for (int bb = 0; bb < 8; bb++) {
                float e0, e1;
                UNPACK2(e0, e1, acc2[bb]);
                g_gpart[(size_t)(kz * 32 + b0 + bb) * 2048 + col] = e0 + e1;
            }
            __syncthreads();
        }
        gbar();

        // ---- P1: gate reduce + LSTM cell; CTAs 96-127 reset prev-step copy slots ----
        if (flat < 16384) {
            int b = flat >> 9, j = flat & 511;
            float gi = g_bcomb[j], gf = g_bcomb[512 + j], gg = g_bcomb[1024 + j], go = g_bcomb[1536 + j];
#pragma unroll
            for (int p = 0; p < 4; p++) {
                const float* gp = g_gpart + (size_t)(p * 32 + b) * 2048;
                gi += gp[j]; gf += gp[512 + j]; gg += gp[1024 + j]; go += gp[1536 + j];
            }
            float c = g_c[flat];
            float si = 1.f / (1.f + __expf(-gi));
            float sf = 1.f / (1.f + __expf(-gf));
            float so = 1.f / (1.f + __expf(-go));
            c = sf * c + si * tanhf(gg);
            float h = so * tanhf(c);
            g_c[flat] = c;
            g_h[flat] = h;
        } else if (cta >= 96 && cta < 128) {
            int idx = (cta - 96) * 256 + tid;     // 8192 touched slots from prev step
            int b = idx >> 8;
            g_copy[(size_t)b * VEXT + ext[idx]] = -NEGC;
        }
        gbar();

        // ---- P2: energy ----
        for (int wj = gwarp; wj < 8192; wj += NCTA * 8) {
            int b = wj >> 8;
            const float4* h4 = (const float4*)(g_h + b * 512);
            const float4* m4 = (const float4*)(g_mem + (size_t)wj * 512);
            float acc = 0.f;
#pragma unroll
            for (int i = 0; i < 4; i++) {
                float4 a = m4[lane + 32 * i];
                float4 x = h4[lane + 32 * i];
                acc += a.x * x.x + a.y * x.y + a.z * x.z + a.w * x.w;
            }
#pragma unroll
            for (int o = 16; o; o >>= 1) acc += __shfl_xor_sync(0xffffffffu, acc, o);
            if (!lane) g_energy[wj] = acc - NEGC * (1.f - mask[wj]);
        }
        gbar();

        // ---- P3: softmax + scatter (32 CTAs) ----
        if (cta < 32) {
            int b = cta;
            float* sr = sbuf;
            float e = g_energy[b * 256 + tid];
            float m = e;
#pragma unroll
            for (int o = 16; o; o >>= 1) m = fmaxf(m, __shfl_xor_sync(0xffffffffu, m, o));
            if (!lane) sr[wid] = m;
            __syncthreads();
            if (tid < 8) {
                float mm = sr[tid];
#pragma unroll
                for (int o = 4; o; o >>= 1) mm = fmaxf(mm, __shfl_xor_sync(0xffu, mm, o));
                if (!tid) sr[8] = mm;
            }
            __syncthreads();
            float mx = sr[8];
            float pexp = __expf(e - mx);
            float ssum = pexp;
#pragma unroll
            for (int o = 16; o; o >>= 1) ssum += __shfl_xor_sync(0xffffffffu, ssum, o);
            __syncthreads();
            if (!lane) sr[wid] = ssum;
            __syncthreads();
            if (tid < 8) {
                float s2 = sr[tid];
#pragma unroll
                for (int o = 4; o; o >>= 1) s2 += __shfl_xor_sync(0xffu, s2, o);
                if (!tid) sr[9] = s2;
            }
            __syncthreads();
            g_attnw[b * 256 + tid] = pexp / sr[9];
            float* addr = &g_copy[(size_t)b * VEXT + ext[b * 256 + tid]];
            if (e >= 0.f) atomicMax((int*)addr, __float_as_int(e));
            else          atomicMin((unsigned int*)addr, __float_as_uint(e));
            __syncthreads();
        }
        gbar();

        // ---- P4: ctx = attn @ memories ----
        if (flat < 16384) {
            int b = flat >> 9, hd = flat & 511;
            const float* aw = g_attnw + b * 256;
            const float* mb = g_mem + (size_t)b * Ss * Hh + hd;
            float a0 = 0.f, a1 = 0.f;
#pragma unroll 8
            for (int s = 0; s < 256; s += 2) {
                a0 += aw[s] * mb[(size_t)s * 512];
                a1 += aw[s + 1] * mb[(size_t)(s + 1) * 512];
            }
            g_ctx[flat] = a0 + a1;
        }
        gbar();

        // ---- P5: cat partials (fp32x2, 32 CTAs) ----
        if (cta < 32) {
            float (*C)[256] = (float(*)[256])sbuf;
            int cc = cta & 1, bg = (cta >> 1) & 3, kz = cta >> 3;
            int b0 = bg * 8, kbase = kz * 256;
            for (int idx = tid; idx < 8 * 256; idx += NTHR) {
                int bb = idx >> 8, kl = idx & 255, k = kbase + kl, b = b0 + bb;
                C[bb][kl] = (k < 512) ? g_h[b * 512 + k] : g_ctx[b * 512 + k - 512];
            }
            __syncthreads();
            int col = cc * 256 + tid;
            unsigned long long acc2[8] = {};
            const float* W = catW + (size_t)kbase * 512 + col;
            for (int kl = 0; kl < 256; kl += 4) {
                float w0 = W[0], w1 = W[512], w2 = W[1024], w3 = W[1536];
                W += 4 * 512;
                unsigned long long w01, w23;
                PACK2(w01, w0, w1);
                PACK2(w23, w2, w3);
#pragma unroll
                for (int bb = 0; bb < 8; bb++) {
                    ulonglong2 xv = *(const ulonglong2*)&C[bb][kl];
                    FMA2(acc2[bb], xv.x, w01);
                    FMA2(acc2[bb], xv.y, w23);
                }
            }
#pragma unroll
            for (int bb = 0; bb < 8; bb++) {
                float e0, e1;
                UNPACK2(e0, e1, acc2[bb]);
                g_cpart[(size_t)(kz * 32 + b0 + bb) * 512 + col] = e0 + e1;
            }
            __syncthreads();
        }
        gbar();

        // ---- P6: cat reduce + tanh + bf16 split ----
        if (flat < 16384) {
            int b = flat >> 9, col = flat & 511;
            float acc = catb[col];
#pragma unroll
            for (int p = 0; p < 4; p++) acc += g_cpart[(size_t)(p * 32 + b) * 512 + col];
            float s = tanhf(acc);
            __nv_bfloat16 hi, lo;
            bf16split(s, &hi, &lo);
            g_shi[flat] = hi;
            g_slo[flat] = lo;
        }
        gbar();

        // ---- P7: logit mma (125 CTAs) + OOV tail ----
        if (cta < 125) {
            int n0 = cta * 256 + wid * 32;
            float acc[2][4][4];
#pragma unroll
            for (int mt = 0; mt < 2; mt++)
#pragma unroll
                for (int nt = 0; nt < 4; nt++)
#pragma unroll
                    for (int i = 0; i < 4; i++) acc[mt][nt][i] = 0.f;
            const uint32_t* shi = (const uint32_t*)g_shi;
            const uint32_t* slo = (const uint32_t*)g_slo;
            const uint32_t* WhiT = (const uint32_t*)g_WhiT;
            const uint32_t* WloT = (const uint32_t*)g_WloT;
#pragma unroll 4
            for (int kt = 0; kt < 32; kt++) {
                int kw = kt * 8 + qc;
                uint32_t ahi[2][4], alo[2][4];
#pragma unroll
                for (int mt = 0; mt < 2; mt++) {
                    int r0 = mt * 16 + qr;
                    ahi[mt][0] = shi[r0 * 256 + kw];
                    ahi[mt][1] = shi[(r0 + 8) * 256 + kw];
                    ahi[mt][2] = shi[r0 * 256 + kw + 4];
                    ahi[mt][3] = shi[(r0 + 8) * 256 + kw + 4];
                    alo[mt][0] = slo[r0 * 256 + kw];
                    alo[mt][1] = slo[(r0 + 8) * 256 + kw];
                    alo[mt][2] = slo[r0 * 256 + kw + 4];
                    alo[mt][3] = slo[(r0 + 8) * 256 + kw + 4];
                }
#pragma unroll
                for (int nt = 0; nt < 4; nt++) {
                    size_t nrow = (size_t)(n0 + nt * 8 + qr) * 256;
                    uint32_t bhi[2], blo[2];
                    bhi[0] = WhiT[nrow + kw];
                    bhi[1] = WhiT[nrow + kw + 4];
                    blo[0] = WloT[nrow + kw];
                    blo[1] = WloT[nrow + kw + 4];
#pragma unroll
                    for (int mt = 0; mt < 2; mt++) {
                        mma16816(acc[mt][nt], ahi[mt], bhi);
                        mma16816(acc[mt][nt], ahi[mt], blo);
                        mma16816(acc[mt][nt], alo[mt], bhi);
                    }
                }
            }
#pragma unroll
            for (int mt = 0; mt < 2; mt++) {
#pragma unroll
                for (int nt = 0; nt < 4; nt++) {
                    int v = n0 + nt * 8 + qc * 2;
                    float lb0 = logb[v], lb1 = logb[v + 1];
#pragma unroll
                    for (int half = 0; half < 2; half++) {
                        int b = mt * 16 + qr + half * 8;
                        const float* crow = g_copy + (size_t)b * VEXT;
                        float c0 = crow[v], c1 = crow[v + 1];
                        c0 = (c0 <= -5e11f) ? 0.f : c0;
                        c1 = (c1 <= -5e11f) ? 0.f : c1;
                        float2 o;
                        o.x = acc[mt][nt][half * 2 + 0] + lb0 + c0;
                        o.y = acc[mt][nt][half * 2 + 1] + lb1 + c1;
                        *(float2*)&out[(size_t)b * Tt * VEXT + (size_t)t * VEXT + v] = o;
                    }
                }
            }
        } else {
            int oidx = flat - 125 * 256;
            if (oidx >= 0 && oidx < Bz * OOV) {
                int b = oidx / OOV, j = oidx - b * OOV;
                float cv = g_copy[(size_t)b * VEXT + Vv + j];
                cv = (cv <= -5e11f) ? 0.f : cv;
                out[(size_t)b * Tt * VEXT + (size_t)t * VEXT + Vv + j] = cv;
            }
        }
        gbar();
    }
}

// ---------------- launcher ----------------
extern "C" void kernel_launch(void* const* d_in, const int* in_sizes, int n_in,
                              void* d_out, int out_size) {
    const int*   trg   = (const int*)d_in[0];
    const int*   ext   = (const int*)d_in[1];
    const float* encO  = (const float*)d_in[2];
    const float* mask  = (const float*)d_in[3];
    const float* h0    = (const float*)d_in[4];
    const float* c0    = (const float*)d_in[5];
    const float* emb   = (const float*)d_in[6];
    const float* encW  = (const float*)d_in[7];
    const float* encb  = (const float*)d_in[8];
    const float* redW  = (const float*)d_in[9];
    const float* redb  = (const float*)d_in[10];
    const float* Wx    = (const float*)d_in[11];
    const float* Wh    = (const float*)d_in[12];
    const float* bl    = (const float*)d_in[13];
    const float* catW  = (const float*)d_in[14];
    const float* catb  = (const float*)d_in[15];
    const float* logW  = (const float*)d_in[16];
    const float* logb  = (const float*)d_in[17];
    float* out = (float*)d_out;

    k_init<<<64, 256>>>(h0, c0);                                                      // 0
    k_resetfull<<<(Bz * VEXT + 255) / 256, 256>>>();                                  // 1
    k_gemm<<<dim3(512 / 64, 8192 / 64), 256>>>(encO, encW, encb, 8192, 512, 512, 0);  // 2
    k_gemm<<<dim3(2048 / 64, 768 / 64), 256>>>(redW, Wx, nullptr, 768, 256, 2048, 1); // 3
    k_prep<<<20104, 256>>>(redb, Wx, bl, logW, Wh);                                   // 4
    k_step<<<NCTA, NTHR>>>(trg, ext, mask, emb, catW, catb, logb, out);               // 5
}